// round 2
// baseline (speedup 1.0000x reference)
#include <cuda_runtime.h>
#include <cstdint>

#define N_BINS 1000
#define EPS_F 1e-4f

// Persistent scratch: 3 x 1000 sigmoid table (no cudaMalloc allowed).
__device__ float g_S[3 * N_BINS];

// ---------------------------------------------------------------------------
// Kernel 1: build the 3x1000 sigmoid lookup table.
// S[j][b] = sigmoid((ub_j - logit(t_b)) / (ub_j - lb_j + eps))
// with (lb,ub) -> (min,max) swap as in get_parameters.
// Only 3000 evaluations -> precise logf/expf.
// ---------------------------------------------------------------------------
__global__ void pm_build_table(const float* __restrict__ bin_centers,
                               const float* __restrict__ lower_bounds,
                               const float* __restrict__ upper_bounds) {
    int i = blockIdx.x * blockDim.x + threadIdx.x;
    if (i >= 3 * N_BINS) return;
    int j = i / N_BINS;   // bound index 0..2
    int b = i % N_BINS;   // bin index
    float lbv = lower_bounds[j];
    float ubv = upper_bounds[j];
    float lo = fminf(lbv, ubv);
    float hi = fmaxf(lbv, ubv);
    float t = bin_centers[b];
    float g = logf(t / (1.0f - t));
    float x = (hi - g) / (hi - lo + EPS_F);
    g_S[i] = 1.0f / (1.0f + expf(-x));
}

// ---------------------------------------------------------------------------
// Kernel 2: streaming gather + product (int32 indices).
// Each thread handles 4 rows (4 x 3 int32 = 48 bytes = 3 x uint4),
// gathers from the shared-memory table, writes one float4.
// Row layout across the three uint4s:
//   v0 = [i0.a, i0.b, i0.c, i1.a]
//   v1 = [i1.b, i1.c, i2.a, i2.b]
//   v2 = [i2.c, i3.a, i3.b, i3.c]
// ---------------------------------------------------------------------------
__global__ void __launch_bounds__(256)
pm_eval_kernel(const uint4* __restrict__ idx_v, float4* __restrict__ out_v,
               int n_quads) {
    __shared__ float sS[3 * N_BINS];
    for (int i = threadIdx.x; i < 3 * N_BINS; i += blockDim.x)
        sS[i] = g_S[i];
    __syncthreads();

    const float* __restrict__ S0 = sS;
    const float* __restrict__ S1 = sS + N_BINS;
    const float* __restrict__ S2 = sS + 2 * N_BINS;

    int q = blockIdx.x * blockDim.x + threadIdx.x;
    if (q >= n_quads) return;

    const uint4* p = idx_v + (size_t)q * 3;
    uint4 v0 = p[0];
    uint4 v1 = p[1];
    uint4 v2 = p[2];

    float4 o;
    o.x = S0[v0.x] * S1[v0.y] * S2[v0.z];
    o.y = S0[v0.w] * S1[v1.x] * S2[v1.y];
    o.z = S0[v1.z] * S1[v1.w] * S2[v2.x];
    o.w = S0[v2.y] * S1[v2.z] * S2[v2.w];
    out_v[q] = o;
}

// Scalar tail (only runs if out_size % 4 != 0; for this problem it won't).
__global__ void pm_eval_tail(const int* __restrict__ idx,
                             float* __restrict__ out, int start, int n) {
    int i = start + blockIdx.x * blockDim.x + threadIdx.x;
    if (i >= n) return;
    int a = idx[3 * (size_t)i + 0];
    int b = idx[3 * (size_t)i + 1];
    int c = idx[3 * (size_t)i + 2];
    out[i] = g_S[a] * g_S[N_BINS + b] * g_S[2 * N_BINS + c];
}

extern "C" void kernel_launch(void* const* d_in, const int* in_sizes, int n_in,
                              void* d_out, int out_size) {
    const float* bin_centers  = (const float*)d_in[0];
    const int*   obs_idx      = (const int*)d_in[1];   // int64 request coerced to int32 by JAX (x64 off)
    const float* lower_bounds = (const float*)d_in[2];
    const float* upper_bounds = (const float*)d_in[3];
    float* out = (float*)d_out;

    // 1) Build the 3000-entry sigmoid table.
    pm_build_table<<<(3 * N_BINS + 255) / 256, 256>>>(bin_centers, lower_bounds,
                                                      upper_bounds);

    // 2) Streaming gather-product.
    int n = out_size;
    int n_quads = n / 4;
    if (n_quads > 0) {
        int blocks = (n_quads + 255) / 256;
        pm_eval_kernel<<<blocks, 256>>>((const uint4*)obs_idx, (float4*)out,
                                        n_quads);
    }
    int tail = n - n_quads * 4;
    if (tail > 0) {
        pm_eval_tail<<<1, 256>>>(obs_idx, out, n_quads * 4, n);
    }
}